// round 3
// baseline (speedup 1.0000x reference)
#include <cuda_runtime.h>
#include <cuda_bf16.h>
#include <cstdint>

// Problem constants
#define D_MODEL 256
#define D_HIDDEN 1024
#define TM 64            // tokens per CTA
#define XS 264           // Xs row stride (floats), 256 + 8 pad
#define HSd 136          // Hs row stride, 128 + 8 pad
#define W1S 72           // W1 tile row stride, 64 + 8 pad
#define W2S 264          // W2 tile row stride, 256 + 8 pad

// Precomputed masked weights (tf32-rounded), 1MB each
__device__ float g_w1[D_HIDDEN * D_MODEL];    // [h][d] = w1*mask
__device__ float g_w2t[D_HIDDEN * D_MODEL];   // [h][d] = w2[d][h]*mask[h][d]

__device__ __forceinline__ float tf32r(float x) {
    uint32_t u;
    asm("cvt.rna.tf32.f32 %0, %1;" : "=r"(u) : "f"(x));
    return __uint_as_float(u);
}

__device__ __forceinline__ void mma_tf32(float c[4],
                                         uint32_t a0, uint32_t a1, uint32_t a2, uint32_t a3,
                                         uint32_t b0, uint32_t b1) {
    asm volatile(
        "mma.sync.aligned.m16n8k8.row.col.f32.tf32.tf32.f32 "
        "{%0,%1,%2,%3}, {%4,%5,%6,%7}, {%8,%9}, {%0,%1,%2,%3};\n"
        : "+f"(c[0]), "+f"(c[1]), "+f"(c[2]), "+f"(c[3])
        : "r"(a0), "r"(a1), "r"(a2), "r"(a3), "r"(b0), "r"(b1));
}

__device__ __forceinline__ uint32_t fbits(float x) { return __float_as_uint(x); }

// ---------------- weight prep: mask + tf32 round ----------------
__global__ void prep_weights(const float* __restrict__ w1,
                             const float* __restrict__ w2,
                             const int* __restrict__ mask) {
    int idx = blockIdx.x * blockDim.x + threadIdx.x;
    if (idx >= D_HIDDEN * D_MODEL) return;
    int h = idx / D_MODEL;
    int d = idx % D_MODEL;
    float m = (mask[idx] != 0) ? 1.0f : 0.0f;
    g_w1[idx]  = tf32r(w1[idx] * m);
    g_w2t[idx] = tf32r(w2[(size_t)d * D_HIDDEN + h] * m);
}

// ---------------- fused masked MLP ----------------
__global__ __launch_bounds__(256, 1)
void ffd_fused(const float* __restrict__ x,
               const float* __restrict__ b1,
               const float* __restrict__ b2,
               float* __restrict__ out,
               int n_tokens) {
    extern __shared__ float sm[];
    float* Xs = sm;                         // [64][XS]
    float* Hs = sm + TM * XS;               // [64][HSd]
    float* Wu = Hs + TM * HSd;              // union: W1 tile [128][W1S] / W2 tile [32][W2S]

    const int tid  = threadIdx.x;
    const int lane = tid & 31;
    const int warp = tid >> 5;
    const int g    = lane >> 2;   // groupID
    const int q    = lane & 3;    // thread-in-group
    const int m0   = (warp >> 1) * 16;
    const int wn   = warp & 1;
    const int mt   = blockIdx.x * TM;

    // ---- load X tile (tf32-rounded) ----
    #pragma unroll
    for (int i = 0; i < 16; i++) {
        int lin = tid + i * 256;            // 4096 float4 total
        int row = lin >> 6;
        int c4  = lin & 63;
        int tok = mt + row;
        float4 v = make_float4(0.f, 0.f, 0.f, 0.f);
        if (tok < n_tokens)
            v = *reinterpret_cast<const float4*>(x + (size_t)tok * D_MODEL + c4 * 4);
        v.x = tf32r(v.x); v.y = tf32r(v.y); v.z = tf32r(v.z); v.w = tf32r(v.w);
        *reinterpret_cast<float4*>(Xs + row * XS + c4 * 4) = v;
    }
    __syncthreads();

    float yacc[16][4];
    #pragma unroll
    for (int j = 0; j < 16; j++)
        #pragma unroll
        for (int r = 0; r < 4; r++) yacc[j][r] = 0.f;

    for (int hc = 0; hc < 8; hc++) {        // hidden chunks of 128
        // ======== GEMM1: H[64,128] = Xs @ W1chunk^T ========
        float hacc[8][4];
        #pragma unroll
        for (int j = 0; j < 8; j++)
            #pragma unroll
            for (int r = 0; r < 4; r++) hacc[j][r] = 0.f;

        const int h0 = wn * 64;

        for (int kt = 0; kt < 4; kt++) {    // K tiles of 64 over D=256
            __syncthreads();                // prior Wu readers done
            #pragma unroll
            for (int i = 0; i < 8; i++) {   // 2048 float4: 128 rows x 16
                int lin = tid + i * 256;
                int row = lin >> 4;
                int c4  = lin & 15;
                float4 v = *reinterpret_cast<const float4*>(
                    g_w1 + ((size_t)(hc * 128 + row) * D_MODEL + kt * 64 + c4 * 4));
                *reinterpret_cast<float4*>(Wu + row * W1S + c4 * 4) = v;
            }
            __syncthreads();

            #pragma unroll
            for (int k8 = 0; k8 < 8; k8++) {
                const int kk = kt * 64 + k8 * 8;
                const float* xa = Xs + (m0 + g) * XS + kk + q;
                const float* xb = Xs + (m0 + g + 8) * XS + kk + q;
                uint32_t a0 = fbits(xa[0]);
                uint32_t a2 = fbits(xa[4]);
                uint32_t a1 = fbits(xb[0]);
                uint32_t a3 = fbits(xb[4]);
                #pragma unroll
                for (int j = 0; j < 8; j++) {
                    const float* bp = Wu + (h0 + 8 * j + g) * W1S + k8 * 8 + q;
                    uint32_t b0 = fbits(bp[0]);
                    uint32_t b1r = fbits(bp[4]);
                    mma_tf32(hacc[j], a0, a1, a2, a3, b0, b1r);
                }
            }
        }

        // ---- bias + relu -> Hs (tf32-rounded) ----
        __syncthreads();                    // prior Hs readers (last hc's GEMM2) done
        #pragma unroll
        for (int j = 0; j < 8; j++) {
            int hl  = h0 + 8 * j + 2 * q;
            int hgl = hc * 128 + hl;
            float bb0 = b1[hgl];
            float bb1 = b1[hgl + 1];
            Hs[(m0 + g) * HSd + hl]         = tf32r(fmaxf(hacc[j][0] + bb0, 0.f));
            Hs[(m0 + g) * HSd + hl + 1]     = tf32r(fmaxf(hacc[j][1] + bb1, 0.f));
            Hs[(m0 + g + 8) * HSd + hl]     = tf32r(fmaxf(hacc[j][2] + bb0, 0.f));
            Hs[(m0 + g + 8) * HSd + hl + 1] = tf32r(fmaxf(hacc[j][3] + bb1, 0.f));
        }

        // ======== GEMM2: Y[64,256] += relu(H) @ W2chunk ========
        const int n0 = wn * 128;
        for (int kt2 = 0; kt2 < 4; kt2++) { // K tiles of 32 over 128 hidden
            __syncthreads();                // Hs writes visible + Wu readers done
            #pragma unroll
            for (int i = 0; i < 8; i++) {   // 2048 float4: 32 rows x 64
                int lin = tid + i * 256;
                int row = lin >> 6;
                int c4  = lin & 63;
                float4 v = *reinterpret_cast<const float4*>(
                    g_w2t + ((size_t)(hc * 128 + kt2 * 32 + row) * D_MODEL + c4 * 4));
                *reinterpret_cast<float4*>(Wu + row * W2S + c4 * 4) = v;
            }
            __syncthreads();

            #pragma unroll
            for (int k8 = 0; k8 < 4; k8++) {
                const int kk = kt2 * 32 + k8 * 8;
                const float* ha = Hs + (m0 + g) * HSd + kk + q;
                const float* hb = Hs + (m0 + g + 8) * HSd + kk + q;
                uint32_t a0 = fbits(ha[0]);
                uint32_t a2 = fbits(ha[4]);
                uint32_t a1 = fbits(hb[0]);
                uint32_t a3 = fbits(hb[4]);
                #pragma unroll
                for (int j = 0; j < 16; j++) {
                    const float* bp = Wu + (k8 * 8 + q) * W2S + n0 + 8 * j + g;
                    uint32_t b0 = fbits(bp[0]);
                    uint32_t b1r = fbits(bp[4 * W2S]);
                    mma_tf32(yacc[j], a0, a1, a2, a3, b0, b1r);
                }
            }
        }
    }

    // ---- epilogue: + b2, write out ----
    #pragma unroll
    for (int j = 0; j < 16; j++) {
        int d = wn * 128 + 8 * j + 2 * q;
        float bb0 = b2[d];
        float bb1 = b2[d + 1];
        int t0 = mt + m0 + g;
        int t1 = t0 + 8;
        if (t0 < n_tokens) {
            float2 v = make_float2(yacc[j][0] + bb0, yacc[j][1] + bb1);
            *reinterpret_cast<float2*>(out + (size_t)t0 * D_MODEL + d) = v;
        }
        if (t1 < n_tokens) {
            float2 v = make_float2(yacc[j][2] + bb0, yacc[j][3] + bb1);
            *reinterpret_cast<float2*>(out + (size_t)t1 * D_MODEL + d) = v;
        }
    }
}

extern "C" void kernel_launch(void* const* d_in, const int* in_sizes, int n_in,
                              void* d_out, int out_size) {
    // inputs (metadata order): x, w1, b1, w2, b2, mask
    const float* x    = (const float*)d_in[0];
    const float* w1   = (const float*)d_in[1];
    const float* b1   = (const float*)d_in[2];
    const float* w2   = (const float*)d_in[3];
    const float* b2   = (const float*)d_in[4];
    const int*   mask = (const int*)d_in[5];
    float* out = (float*)d_out;

    const int n_tokens = in_sizes[0] / D_MODEL;

    // precompute masked+tf32 weights
    prep_weights<<<(D_HIDDEN * D_MODEL + 255) / 256, 256>>>(w1, w2, mask);

    // fused MLP
    const int smem_bytes = (TM * XS + TM * HSd + 128 * W1S) * (int)sizeof(float);
    static_assert(128 * W1S >= 32 * W2S, "weight tile union sizing");
    cudaFuncSetAttribute(ffd_fused, cudaFuncAttributeMaxDynamicSharedMemorySize, smem_bytes);

    const int grid = (n_tokens + TM - 1) / TM;
    ffd_fused<<<grid, 256, smem_bytes>>>(x, b1, b2, out, n_tokens);
}

// round 7
// speedup vs baseline: 1.7712x; 1.7712x over previous
#include <cuda_runtime.h>
#include <cuda_bf16.h>
#include <cstdint>

#define D_MODEL  256
#define D_HIDDEN 1024
#define TM       64          // tokens per CTA
#define HSd      132         // Hs row stride (floats): 132 mod 32 banks = 4 -> conflict-free frag loads

// ---- SMEM byte offsets ----
#define XF_OFF     0                         // X A-frag: 64KB
#define HS_OFF     65536                     // Hs: 64*132*4 = 33792
#define RING_OFF   99328                     // 2 x 32KB weight tile ring
#define B1_OFF     164864                    // 4KB
#define B2_OFF     168960                    // 1KB
#define SMEM_TOTAL 169984

// Pre-masked, tf32-rounded weights in MMA fragment-pair layout.
// Tile = 8192 floats (32KB). W1: tile (hc,kt) covers h[hc*128 +128) x d[kt*64 +64).
// W2: tile (hc,kt2) covers k=h[hc*128+kt2*32 +32) x n=d[0,256).
// float4 slot layout packs B-fragments for an (even,odd) MMA j-pair.
__device__ float g_w1f[D_HIDDEN * D_MODEL];
__device__ float g_w2f[D_HIDDEN * D_MODEL];

// ======================= helpers =======================
__device__ __forceinline__ uint32_t tf32bits(float x) {
    uint32_t u;
    asm("cvt.rna.tf32.f32 %0, %1;" : "=r"(u) : "f"(x));
    return u;
}
__device__ __forceinline__ float tf32r(float x) { return __uint_as_float(tf32bits(x)); }

__device__ __forceinline__ uint32_t smem_u32(const void* p) {
    uint32_t a;
    asm("{ .reg .u64 t; cvta.to.shared.u64 t, %1; cvt.u32.u64 %0, t; }" : "=r"(a) : "l"(p));
    return a;
}

__device__ __forceinline__ void mma_t(float c[4], const float4& A, float b0, float b1) {
    asm volatile(
        "mma.sync.aligned.m16n8k8.row.col.f32.tf32.tf32.f32 "
        "{%0,%1,%2,%3}, {%4,%5,%6,%7}, {%8,%9}, {%0,%1,%2,%3};\n"
        : "+f"(c[0]), "+f"(c[1]), "+f"(c[2]), "+f"(c[3])
        : "r"(__float_as_uint(A.x)), "r"(__float_as_uint(A.y)),
          "r"(__float_as_uint(A.z)), "r"(__float_as_uint(A.w)),
          "r"(__float_as_uint(b0)), "r"(__float_as_uint(b1)));
}

#define CP_COMMIT() asm volatile("cp.async.commit_group;" ::: "memory")
#define CP_WAIT0()  asm volatile("cp.async.wait_group 0;" ::: "memory")

// Issue one 32KB weight tile (t in 0..63) into ring buffer t&1.
__device__ __forceinline__ void issue_tile(int t, int tid, uint32_t ring) {
    const float* src = ((t & 7) < 4)
        ? (g_w1f + (((t >> 3) * 4 + (t & 7)) << 13))
        : (g_w2f + (((t >> 3) * 4 + ((t & 7) - 4)) << 13));
    uint64_t gs = __cvta_generic_to_global(src) + (uint64_t)tid * 16;
    uint32_t ds = ring + (t & 1) * 32768 + tid * 16;
    #pragma unroll
    for (int i = 0; i < 16; i++)
        asm volatile("cp.async.cg.shared.global [%0], [%1], 16;"
                     :: "r"(ds + i * 2048), "l"(gs + i * 2048));
    CP_COMMIT();
}

// ============ weight prep: mask + tf32 round + fragment-pair pack ============
__global__ void prep_weights(const float* __restrict__ w1,
                             const float* __restrict__ w2,
                             const int* __restrict__ mask) {
    int idx = blockIdx.x * blockDim.x + threadIdx.x;
    if (idx >= D_HIDDEN * D_MODEL) return;
    int h = idx >> 8;
    int d = idx & 255;
    float m = (mask[idx] != 0) ? 1.0f : 0.0f;

    // ---- W1 frag: value w1[h][d]*m at MMA-B position (n-row = h, k = d) ----
    {
        float v = tf32r(w1[idx] * m);
        int hc = h >> 7, hin = h & 127;
        int jp = hin >> 4, par = (hin >> 3) & 1, g = hin & 7;
        int kt = d >> 6, din = d & 63;
        int k8 = din >> 3, q = din & 3, half = (din >> 2) & 1;
        g_w1f[(((hc * 4 + kt) << 13)) +
              ((jp * 8 + k8) * 32 + g * 4 + q) * 4 + par * 2 + half] = v;
    }
    // ---- W2 frag: value w2[d][h]*m at MMA-B position (n-row = d, k = h) ----
    {
        float v = tf32r(w2[(size_t)d * D_HIDDEN + h] * m);
        int hc = h >> 7, hin = h & 127;
        int kt2 = hin >> 5, kin = hin & 31;
        int k8 = kin >> 3, q = kin & 3, half = (kin >> 2) & 1;
        int jp = d >> 4, par = (d >> 3) & 1, g = d & 7;
        g_w2f[(((hc * 4 + kt2) << 13)) +
              ((jp * 4 + k8) * 32 + g * 4 + q) * 4 + par * 2 + half] = v;
    }
}

// ======================= fused MLP =======================
__global__ __launch_bounds__(128, 1)
void ffd_mma(const float* __restrict__ x,
             const float* __restrict__ b1,
             const float* __restrict__ b2,
             float* __restrict__ out,
             int n_tokens) {
    extern __shared__ char smem[];
    float* XsF = (float*)(smem + XF_OFF);
    float* Hs  = (float*)(smem + HS_OFF);
    float* b1s = (float*)(smem + B1_OFF);
    float* b2s = (float*)(smem + B2_OFF);
    const uint32_t ring = smem_u32(smem + RING_OFF);

    const int tid    = threadIdx.x;
    const int warp   = tid >> 5;
    const int lane   = tid & 31;
    const int g      = lane >> 2;
    const int q      = lane & 3;
    const int warp_m = warp >> 1;     // 0..1: which 32-row block
    const int wn     = warp & 1;      // n-half
    const int mt     = blockIdx.x * TM;

    // Prefetch weight tile 0 first (overlaps X fill)
    issue_tile(0, tid, ring);

    // ---- X tile -> A-fragment layout (tf32-rounded) ----
    #pragma unroll
    for (int i = 0; i < 32; i++) {
        int lin = tid + i * 128;          // 4096 float4 total
        int row = lin >> 6, c4 = lin & 63;
        int tok = mt + row;
        float4 v = make_float4(0.f, 0.f, 0.f, 0.f);
        if (tok < n_tokens)
            v = *reinterpret_cast<const float4*>(x + (size_t)tok * D_MODEL + c4 * 4);
        int k8 = c4 >> 1;
        int slot = (c4 & 1) * 2 + ((row >> 3) & 1);
        int base = ((row >> 4) * 32 + k8) * 32 + (row & 7) * 4;
        XsF[(base + 0) * 4 + slot] = tf32r(v.x);
        XsF[(base + 1) * 4 + slot] = tf32r(v.y);
        XsF[(base + 2) * 4 + slot] = tf32r(v.z);
        XsF[(base + 3) * 4 + slot] = tf32r(v.w);
    }
    #pragma unroll
    for (int i = tid; i < D_HIDDEN; i += 128) b1s[i] = b1[i];
    b2s[tid] = b2[tid];
    b2s[tid + 128] = b2[tid + 128];
    __syncthreads();

    float yacc[2][16][4];
    #pragma unroll
    for (int a = 0; a < 2; a++)
        #pragma unroll
        for (int j = 0; j < 16; j++)
            #pragma unroll
            for (int r = 0; r < 4; r++) yacc[a][j][r] = 0.f;

    const float4* XsF4 = (const float4*)XsF;
    int t = 0;

    for (int hc = 0; hc < 8; hc++) {
        float hacc[2][8][4];
        #pragma unroll
        for (int a = 0; a < 2; a++)
            #pragma unroll
            for (int j = 0; j < 8; j++)
                #pragma unroll
                for (int r = 0; r < 4; r++) hacc[a][j][r] = 0.f;

        // ======== GEMM1: H[64,128] += X[64,256] @ W1c^T ========
        for (int kt = 0; kt < 4; kt++, t++) {
            CP_WAIT0();
            __syncthreads();
            if (t + 1 < 64) issue_tile(t + 1, tid, ring);
            const float4* Bt = (const float4*)(smem + RING_OFF + (t & 1) * 32768);

            #pragma unroll
            for (int k8l = 0; k8l < 8; k8l++) {
                const int k8 = kt * 8 + k8l;
                float4 A0 = XsF4[((warp_m * 2 + 0) * 32 + k8) * 32 + lane];
                float4 A1 = XsF4[((warp_m * 2 + 1) * 32 + k8) * 32 + lane];
                #pragma unroll
                for (int jp = 0; jp < 4; jp++) {
                    float4 B2 = Bt[(((wn << 2) | jp) * 8 + k8l) * 32 + lane];
                    mma_t(hacc[0][2 * jp],     A0, B2.x, B2.y);
                    mma_t(hacc[0][2 * jp + 1], A0, B2.z, B2.w);
                    mma_t(hacc[1][2 * jp],     A1, B2.x, B2.y);
                    mma_t(hacc[1][2 * jp + 1], A1, B2.z, B2.w);
                }
            }
        }

        // ---- bias + relu -> Hs (row-major, tf32-rounded) ----
        #pragma unroll
        for (int mt2 = 0; mt2 < 2; mt2++) {
            int r0 = warp_m * 32 + mt2 * 16 + g;
            #pragma unroll
            for (int j = 0; j < 8; j++) {
                int hl = wn * 64 + 8 * j + 2 * q;
                float bb0 = b1s[hc * 128 + hl];
                float bb1 = b1s[hc * 128 + hl + 1];
                float2 v0, v1;
                v0.x = tf32r(fmaxf(hacc[mt2][j][0] + bb0, 0.f));
                v0.y = tf32r(fmaxf(hacc[mt2][j][1] + bb1, 0.f));
                v1.x = tf32r(fmaxf(hacc[mt2][j][2] + bb0, 0.f));
                v1.y = tf32r(fmaxf(hacc[mt2][j][3] + bb1, 0.f));
                *reinterpret_cast<float2*>(&Hs[r0 * HSd + hl]) = v0;
                *reinterpret_cast<float2*>(&Hs[(r0 + 8) * HSd + hl]) = v1;
            }
        }

        // ======== GEMM2: Y[64,256] += relu(H)[64,128] @ W2c ========
        for (int kt2 = 0; kt2 < 4; kt2++, t++) {
            CP_WAIT0();
            __syncthreads();                 // Hs visible + ring buffer free + tile ready
            if (t + 1 < 64) issue_tile(t + 1, tid, ring);
            const float4* Bt = (const float4*)(smem + RING_OFF + (t & 1) * 32768);

            #pragma unroll
            for (int k8l = 0; k8l < 4; k8l++) {
                const int kk = kt2 * 32 + k8l * 8;
                float4 a[2];
                #pragma unroll
                for (int mt2 = 0; mt2 < 2; mt2++) {
                    int r0 = warp_m * 32 + mt2 * 16 + g;
                    a[mt2].x = Hs[r0 * HSd + kk + q];
                    a[mt2].z = Hs[r0 * HSd + kk + q + 4];
                    a[mt2].y = Hs[(r0 + 8) * HSd + kk + q];
                    a[mt2].w = Hs[(r0 + 8) * HSd + kk + q + 4];
                }
                #pragma unroll
                for (int jpl = 0; jpl < 8; jpl++) {
                    float4 B2 = Bt[(((wn << 3) | jpl) * 4 + k8l) * 32 + lane];
                    mma_t(yacc[0][2 * jpl],     a[0], B2.x, B2.y);
                    mma_t(yacc[0][2 * jpl + 1], a[0], B2.z, B2.w);
                    mma_t(yacc[1][2 * jpl],     a[1], B2.x, B2.y);
                    mma_t(yacc[1][2 * jpl + 1], a[1], B2.z, B2.w);
                }
            }
        }
    }

    // ---- epilogue: + b2, write out ----
    #pragma unroll
    for (int mt2 = 0; mt2 < 2; mt2++) {
        int r0 = warp_m * 32 + mt2 * 16 + g;
        int tok0 = mt + r0;
        int tok1 = tok0 + 8;
        #pragma unroll
        for (int j = 0; j < 16; j++) {
            int d = wn * 128 + 8 * j + 2 * q;
            float bb0 = b2s[d];
            float bb1 = b2s[d + 1];
            if (tok0 < n_tokens) {
                float2 v = make_float2(yacc[mt2][j][0] + bb0, yacc[mt2][j][1] + bb1);
                *reinterpret_cast<float2*>(out + (size_t)tok0 * D_MODEL + d) = v;
            }
            if (tok1 < n_tokens) {
                float2 v = make_float2(yacc[mt2][j][2] + bb0, yacc[mt2][j][3] + bb1);
                *reinterpret_cast<float2*>(out + (size_t)tok1 * D_MODEL + d) = v;
            }
        }
    }
}

extern "C" void kernel_launch(void* const* d_in, const int* in_sizes, int n_in,
                              void* d_out, int out_size) {
    // inputs (metadata order): x, w1, b1, w2, b2, mask
    const float* x    = (const float*)d_in[0];
    const float* w1   = (const float*)d_in[1];
    const float* b1   = (const float*)d_in[2];
    const float* w2   = (const float*)d_in[3];
    const float* b2   = (const float*)d_in[4];
    const int*   mask = (const int*)d_in[5];
    float* out = (float*)d_out;

    const int n_tokens = in_sizes[0] / D_MODEL;

    prep_weights<<<(D_HIDDEN * D_MODEL + 255) / 256, 256>>>(w1, w2, mask);

    cudaFuncSetAttribute(ffd_mma, cudaFuncAttributeMaxDynamicSharedMemorySize, SMEM_TOTAL);
    const int grid = (n_tokens + TM - 1) / TM;
    ffd_mma<<<grid, 128, SMEM_TOTAL>>>(x, b1, b2, out, n_tokens);
}